// round 5
// baseline (speedup 1.0000x reference)
#include <cuda_runtime.h>
#include <cstdint>

// ---------------------------------------------------------------------------
// EmbedderMessageFunction (TGN message): fused gather + time-encode +
// MLP(512 -> relu 512 -> 256), TF32 mma.sync (m16n8k8), M-tile = 64 events.
// ---------------------------------------------------------------------------

#define E_TILE   64
#define THREADS  256

// smem layout (bytes)
#define OFF_A     0            // A fragment region: 4 mt * 64 ks * 32 lanes * 16B = 131072
#define OFF_STAG  131072       // staging 64 x 132 floats = 33792
#define OFF_B1    164864       // 512 floats
#define OFF_B2    166912       // 256 floats
#define OFF_FREQ  167936       // 128 floats
#define OFF_PHASE 168448       // 128 floats
#define OFF_DT    168960       // 64 floats
#define OFF_SRC   169216       // 64 ints
#define OFF_DST   169472
#define OFF_EID   169728
#define SMEM_BYTES 169984

// fragment-major tf32 weights (built once per launch by prep kernel)
// W1F: [ntg 0..63][ks 0..63][lane 0..31][2]   (HIDDEN=512 -> 64 n-tiles)
// W2F: [ntg 0..31][ks 0..63][lane 0..31][2]   (OUT=256    -> 32 n-tiles)
__device__ float g_W1F[64 * 64 * 32 * 2];
__device__ float g_W2F[32 * 64 * 32 * 2];

static __device__ __forceinline__ uint32_t f2tf32(float x) {
    uint32_t r;
    asm("cvt.rna.tf32.f32 %0, %1;" : "=r"(r) : "f"(x));
    return r;
}

static __device__ __forceinline__ void mma8(float* d, uint4 a, float2 b) {
    asm volatile(
        "mma.sync.aligned.m16n8k8.row.col.f32.tf32.tf32.f32 "
        "{%0,%1,%2,%3}, {%4,%5,%6,%7}, {%8,%9}, {%0,%1,%2,%3};"
        : "+f"(d[0]), "+f"(d[1]), "+f"(d[2]), "+f"(d[3])
        : "r"(a.x), "r"(a.y), "r"(a.z), "r"(a.w),
          "r"(__float_as_uint(b.x)), "r"(__float_as_uint(b.y)));
}

// ---------------------------- prep kernel ----------------------------------
// B fragment layout for mma.m16n8k8.row.col:
//   b0: (row = lane%4,     col = lane/4)  of the 8x8 k-by-n tile
//   b1: (row = lane%4 + 4, col = lane/4)

__global__ void prep_weights_kernel(const float* __restrict__ W1,
                                    const float* __restrict__ W2) {
    int t0 = blockIdx.x * blockDim.x + threadIdx.x;
    int stride = gridDim.x * blockDim.x;
    for (int t = t0; t < 64 * 64 * 32; t += stride) {
        int lane = t & 31, ks = (t >> 5) & 63, ntg = t >> 11;
        int r = lane & 3, cg = lane >> 2;
        int k0 = ks * 8, n = ntg * 8 + cg;
        g_W1F[2 * t]     = __uint_as_float(f2tf32(W1[(size_t)(k0 + r) * 512 + n]));
        g_W1F[2 * t + 1] = __uint_as_float(f2tf32(W1[(size_t)(k0 + r + 4) * 512 + n]));
    }
    for (int t = t0; t < 32 * 64 * 32; t += stride) {
        int lane = t & 31, ks = (t >> 5) & 63, ntg = t >> 11;
        int r = lane & 3, cg = lane >> 2;
        int k0 = ks * 8, n = ntg * 8 + cg;
        g_W2F[2 * t]     = __uint_as_float(f2tf32(W2[(size_t)(k0 + r) * 256 + n]));
        g_W2F[2 * t + 1] = __uint_as_float(f2tf32(W2[(size_t)(k0 + r + 4) * 256 + n]));
    }
}

// ----------------------------- main kernel ---------------------------------

__global__ __launch_bounds__(THREADS, 1)
void tgn_msg_kernel(const int*   __restrict__ src_nodes,
                    const int*   __restrict__ dst_nodes,
                    const float* __restrict__ timestamps,
                    const int*   __restrict__ event_indices,
                    const int*   __restrict__ nidx,
                    const float* __restrict__ node_emb,
                    const float* __restrict__ last_update,
                    const float* __restrict__ feats,
                    const float* __restrict__ freq,
                    const float* __restrict__ phase,
                    const float* __restrict__ b1,
                    const float* __restrict__ b2,
                    float*       __restrict__ out,
                    int E) {
    extern __shared__ char smem[];
    float* sA    = (float*)(smem + OFF_A);
    float* stag  = (float*)(smem + OFF_STAG);
    float* s_b1  = (float*)(smem + OFF_B1);
    float* s_b2  = (float*)(smem + OFF_B2);
    float* s_frq = (float*)(smem + OFF_FREQ);
    float* s_phs = (float*)(smem + OFF_PHASE);
    float* s_dt  = (float*)(smem + OFF_DT);
    int*   s_src = (int*)(smem + OFF_SRC);
    int*   s_dst = (int*)(smem + OFF_DST);
    int*   s_eid = (int*)(smem + OFF_EID);

    const int tid  = threadIdx.x;
    const int warp = tid >> 5;
    const int lane = tid & 31;
    const int gid  = lane >> 2;   // group id (row within fragment)
    const int tig  = lane & 3;    // thread in group

    const int base = blockIdx.x * E_TILE;

    // ---- preamble: indices / scalars into smem ----
    if (tid < E_TILE) {
        int e = base + tid;
        if (e >= E) e = E - 1;
        s_src[tid] = src_nodes[e];
        s_dst[tid] = dst_nodes[e];
        s_eid[tid] = event_indices[e];
        s_dt[tid]  = timestamps[e] - last_update[nidx[e]];
    }
    if (tid < 128) { s_frq[tid] = freq[tid]; s_phs[tid] = phase[tid]; }
    for (int i = tid; i < 512; i += THREADS) s_b1[i] = b1[i];
    if (tid < 256) s_b2[tid] = b2[tid];
    __syncthreads();

    // ---- build msg [64 x 512] into A-fragment-major smem, 4 chunks of 128 ----
    // chunk 0: src emb, 1: dst emb, 2: time encoding, 3: event feats
    for (int c = 0; c < 4; c++) {
        // stage [64][128] (pitch 132), tf32-rounded, fully coalesced
        #pragma unroll
        for (int i = 0; i < 8; i++) {
            int lin = i * 256 + tid;
            int row = lin >> 5;
            int q   = lin & 31;          // float4 index within 128 cols
            float4 v;
            if (c == 2) {
                float dtv = s_dt[row];
                int t0 = q * 4;
                v.x = cosf(__fmaf_rn(dtv, s_frq[t0 + 0], s_phs[t0 + 0]));
                v.y = cosf(__fmaf_rn(dtv, s_frq[t0 + 1], s_phs[t0 + 1]));
                v.z = cosf(__fmaf_rn(dtv, s_frq[t0 + 2], s_phs[t0 + 2]));
                v.w = cosf(__fmaf_rn(dtv, s_frq[t0 + 3], s_phs[t0 + 3]));
            } else {
                const float* p =
                    (c == 0) ? node_emb + (size_t)s_src[row] * 128 :
                    (c == 1) ? node_emb + (size_t)s_dst[row] * 128 :
                               feats    + (size_t)s_eid[row] * 128;
                v = *(const float4*)(p + q * 4);
            }
            uint4 u;
            u.x = f2tf32(v.x); u.y = f2tf32(v.y);
            u.z = f2tf32(v.z); u.w = f2tf32(v.w);
            *(uint4*)(stag + row * 132 + q * 4) = u;
        }
        __syncthreads();

        // repack staging -> fragment-major A (conflict-free, float4 stores)
        #pragma unroll
        for (int i = 0; i < 8; i++) {
            int f   = i * 8 + warp;       // fragment 0..63 of this chunk
            int mt  = f >> 4;             // m-tile 0..3
            int ksl = f & 15;             // local kstep 0..15
            int ra = mt * 16 + gid;
            int ca = ksl * 8 + tig;
            float4 v;
            v.x = stag[ra * 132 + ca];
            v.y = stag[(ra + 8) * 132 + ca];
            v.z = stag[ra * 132 + ca + 4];
            v.w = stag[(ra + 8) * 132 + ca + 4];
            int ks = c * 16 + ksl;
            *(float4*)(sA + ((mt * 64 + ks) * 32 + lane) * 4) = v;
        }
        __syncthreads();
    }

    // ---- GEMM1: h[64x512] = msg @ W1 ;  N-slice 64 per warp ----
    float acc[4][8][4];
    #pragma unroll
    for (int mt = 0; mt < 4; mt++)
        #pragma unroll
        for (int nt = 0; nt < 8; nt++)
            #pragma unroll
            for (int r = 0; r < 4; r++) acc[mt][nt][r] = 0.0f;

    {
        const float* bbase = g_W1F + (size_t)(warp * 8) * 64 * 64;
        #pragma unroll 2
        for (int ks = 0; ks < 64; ks++) {
            uint4 a[4];
            #pragma unroll
            for (int mt = 0; mt < 4; mt++)
                a[mt] = *(const uint4*)(sA + ((mt * 64 + ks) * 32 + lane) * 4);
            float2 b[8];
            #pragma unroll
            for (int nt = 0; nt < 8; nt++)
                b[nt] = *(const float2*)(bbase + ((nt * 64 + ks) * 32 + lane) * 2);
            #pragma unroll
            for (int mt = 0; mt < 4; mt++)
                #pragma unroll
                for (int nt = 0; nt < 8; nt++)
                    mma8(acc[mt][nt], a[mt], b[nt]);
        }
    }

    // ---- relu + b1, write h back into A region (fragment-major) ----
    __syncthreads();   // everyone done reading msg A
    #pragma unroll
    for (int mt = 0; mt < 4; mt++) {
        #pragma unroll
        for (int nt = 0; nt < 8; nt++) {
            #pragma unroll
            for (int cr = 0; cr < 4; cr++) {
                int row = mt * 16 + gid + 8 * (cr >> 1);
                int n   = warp * 64 + nt * 8 + 2 * tig + (cr & 1);
                float v = fmaxf(acc[mt][nt][cr] + s_b1[n], 0.0f);
                int r15 = row & 15;
                int ks  = n >> 3;
                int c0  = n & 7;
                int l2  = (r15 & 7) * 4 + (c0 & 3);
                int rg  = (r15 >> 3) + 2 * (c0 >> 2);
                sA[((mt * 64 + ks) * 32 + l2) * 4 + rg] =
                    __uint_as_float(f2tf32(v));
            }
        }
    }
    __syncthreads();

    // ---- GEMM2: out[64x256] = h @ W2 ;  N-slice 32 per warp ----
    float acc2[4][4][4];
    #pragma unroll
    for (int mt = 0; mt < 4; mt++)
        #pragma unroll
        for (int nt = 0; nt < 4; nt++)
            #pragma unroll
            for (int r = 0; r < 4; r++) acc2[mt][nt][r] = 0.0f;

    {
        const float* bbase = g_W2F + (size_t)(warp * 4) * 64 * 64;
        #pragma unroll 2
        for (int ks = 0; ks < 64; ks++) {
            uint4 a[4];
            #pragma unroll
            for (int mt = 0; mt < 4; mt++)
                a[mt] = *(const uint4*)(sA + ((mt * 64 + ks) * 32 + lane) * 4);
            float2 b[4];
            #pragma unroll
            for (int nt = 0; nt < 4; nt++)
                b[nt] = *(const float2*)(bbase + ((nt * 64 + ks) * 32 + lane) * 2);
            #pragma unroll
            for (int mt = 0; mt < 4; mt++)
                #pragma unroll
                for (int nt = 0; nt < 4; nt++)
                    mma8(acc2[mt][nt], a[mt], b[nt]);
        }
    }

    // ---- epilogue: + b2, store (32B sectors per row, coalesced enough) ----
    #pragma unroll
    for (int mt = 0; mt < 4; mt++) {
        #pragma unroll
        for (int nt = 0; nt < 4; nt++) {
            int n  = warp * 32 + nt * 8 + 2 * tig;
            float bx = s_b2[n], by = s_b2[n + 1];
            int r0 = mt * 16 + gid;
            int e0 = base + r0;
            if (e0 < E) {
                float2 o;
                o.x = acc2[mt][nt][0] + bx;
                o.y = acc2[mt][nt][1] + by;
                *(float2*)(out + (size_t)e0 * 256 + n) = o;
            }
            int e1 = base + r0 + 8;
            if (e1 < E) {
                float2 o;
                o.x = acc2[mt][nt][2] + bx;
                o.y = acc2[mt][nt][3] + by;
                *(float2*)(out + (size_t)e1 * 256 + n) = o;
            }
        }
    }
}

// ------------------------------- launch ------------------------------------

extern "C" void kernel_launch(void* const* d_in, const int* in_sizes, int n_in,
                              void* d_out, int out_size) {
    const int*   src_nodes     = (const int*)d_in[0];
    const int*   dst_nodes     = (const int*)d_in[1];
    const float* timestamps    = (const float*)d_in[2];
    const int*   event_indices = (const int*)d_in[3];
    const int*   nidx          = (const int*)d_in[4];
    const float* node_emb      = (const float*)d_in[5];
    const float* last_update   = (const float*)d_in[6];
    const float* feats         = (const float*)d_in[7];
    const float* freq          = (const float*)d_in[8];
    const float* phase         = (const float*)d_in[9];
    const float* W1            = (const float*)d_in[10];
    const float* b1v           = (const float*)d_in[11];
    const float* W2            = (const float*)d_in[12];
    const float* b2v           = (const float*)d_in[13];
    float* out = (float*)d_out;

    int E = in_sizes[0];

    cudaFuncSetAttribute(tgn_msg_kernel,
                         cudaFuncAttributeMaxDynamicSharedMemorySize, SMEM_BYTES);

    prep_weights_kernel<<<128, 256>>>(W1, W2);

    int nblk = (E + E_TILE - 1) / E_TILE;
    tgn_msg_kernel<<<nblk, THREADS, SMEM_BYTES>>>(
        src_nodes, dst_nodes, timestamps, event_indices, nidx,
        node_emb, last_update, feats, freq, phase, b1v, b2v, out, E);
}

// round 8
// speedup vs baseline: 1.2118x; 1.2118x over previous
#include <cuda_runtime.h>
#include <cstdint>

// ---------------------------------------------------------------------------
// EmbedderMessageFunction (TGN message): fused gather + time-encode +
// MLP(512 -> relu 512 -> 256), TF32 mma.sync (m16n8k8), M-tile = 64 events.
// R6: cp.async pipelined gathers + distance-2 register double-buffered B.
// ---------------------------------------------------------------------------

#define E_TILE   64
#define THREADS  256

// smem layout (bytes)
#define OFF_A     0            // A fragment region: 4 mt * 64 ks * 32 lanes * 16B
#define OFF_SA    131072       // staging A: 64 x 136 floats = 34816
#define OFF_SB    165888       // staging B: 64 x 136 floats = 34816
#define OFF_B1    200704       // 512 floats
#define OFF_B2    202752       // 256 floats
#define OFF_FREQ  203776       // 128 floats
#define OFF_PHASE 204288       // 128 floats
#define OFF_DT    204800       // 64 floats
#define OFF_SRC   205056       // 64 ints
#define OFF_DST   205312
#define OFF_EID   205568
#define SMEM_BYTES 205824

#define STAG_PITCH 136         // floats; 544B rows keep 16B cp.async alignment

// fragment-major tf32 weights (built once per launch by prep kernel)
// W1F: [ntg 0..63][ks 0..63][lane 0..31][2]   (HIDDEN=512 -> 64 n-tiles)
// W2F: [ntg 0..31][ks 0..63][lane 0..31][2]   (OUT=256    -> 32 n-tiles)
__device__ float g_W1F[64 * 64 * 32 * 2];
__device__ float g_W2F[32 * 64 * 32 * 2];

static __device__ __forceinline__ uint32_t f2tf32(float x) {
    uint32_t r;
    asm("cvt.rna.tf32.f32 %0, %1;" : "=r"(r) : "f"(x));
    return r;
}

static __device__ __forceinline__ uint32_t smem_u32(const void* p) {
    uint32_t a;
    asm("{ .reg .u64 t; cvta.to.shared.u64 t, %1; cvt.u32.u64 %0, t; }"
        : "=r"(a) : "l"(p));
    return a;
}

static __device__ __forceinline__ void cp16(uint32_t dst, const void* src) {
    asm volatile("cp.async.cg.shared.global [%0], [%1], 16;"
                 :: "r"(dst), "l"(src) : "memory");
}
#define CP_COMMIT() asm volatile("cp.async.commit_group;" ::: "memory")
#define CP_WAIT(n)  asm volatile("cp.async.wait_group %0;" :: "n"(n) : "memory")

static __device__ __forceinline__ void mma8(float* d, uint4 a, float2 b) {
    asm volatile(
        "mma.sync.aligned.m16n8k8.row.col.f32.tf32.tf32.f32 "
        "{%0,%1,%2,%3}, {%4,%5,%6,%7}, {%8,%9}, {%0,%1,%2,%3};"
        : "+f"(d[0]), "+f"(d[1]), "+f"(d[2]), "+f"(d[3])
        : "r"(a.x), "r"(a.y), "r"(a.z), "r"(a.w),
          "r"(__float_as_uint(b.x)), "r"(__float_as_uint(b.y)));
}

// ---------------------------- prep kernel ----------------------------------
// B fragment layout for mma.m16n8k8.row.col:
//   b0: (row = lane%4,     col = lane/4)  of the 8x8 k-by-n tile
//   b1: (row = lane%4 + 4, col = lane/4)

__global__ void prep_weights_kernel(const float* __restrict__ W1,
                                    const float* __restrict__ W2) {
    int t0 = blockIdx.x * blockDim.x + threadIdx.x;
    int stride = gridDim.x * blockDim.x;
    for (int t = t0; t < 64 * 64 * 32; t += stride) {
        int lane = t & 31, ks = (t >> 5) & 63, ntg = t >> 11;
        int r = lane & 3, cg = lane >> 2;
        int k0 = ks * 8, n = ntg * 8 + cg;
        g_W1F[2 * t]     = __uint_as_float(f2tf32(W1[(size_t)(k0 + r) * 512 + n]));
        g_W1F[2 * t + 1] = __uint_as_float(f2tf32(W1[(size_t)(k0 + r + 4) * 512 + n]));
    }
    for (int t = t0; t < 32 * 64 * 32; t += stride) {
        int lane = t & 31, ks = (t >> 5) & 63, ntg = t >> 11;
        int r = lane & 3, cg = lane >> 2;
        int k0 = ks * 8, n = ntg * 8 + cg;
        g_W2F[2 * t]     = __uint_as_float(f2tf32(W2[(size_t)(k0 + r) * 256 + n]));
        g_W2F[2 * t + 1] = __uint_as_float(f2tf32(W2[(size_t)(k0 + r + 4) * 256 + n]));
    }
}

// ----------------------------- main kernel ---------------------------------

__global__ __launch_bounds__(THREADS, 1)
void tgn_msg_kernel(const int*   __restrict__ src_nodes,
                    const int*   __restrict__ dst_nodes,
                    const float* __restrict__ timestamps,
                    const int*   __restrict__ event_indices,
                    const int*   __restrict__ nidx,
                    const float* __restrict__ node_emb,
                    const float* __restrict__ last_update,
                    const float* __restrict__ feats,
                    const float* __restrict__ freq,
                    const float* __restrict__ phase,
                    const float* __restrict__ b1,
                    const float* __restrict__ b2,
                    float*       __restrict__ out,
                    int E) {
    extern __shared__ char smem[];
    float* sA    = (float*)(smem + OFF_A);
    float* stagA = (float*)(smem + OFF_SA);
    float* stagB = (float*)(smem + OFF_SB);
    float* s_b1  = (float*)(smem + OFF_B1);
    float* s_b2  = (float*)(smem + OFF_B2);
    float* s_frq = (float*)(smem + OFF_FREQ);
    float* s_phs = (float*)(smem + OFF_PHASE);
    float* s_dt  = (float*)(smem + OFF_DT);
    int*   s_src = (int*)(smem + OFF_SRC);
    int*   s_dst = (int*)(smem + OFF_DST);
    int*   s_eid = (int*)(smem + OFF_EID);

    const uint32_t sbA = smem_u32(stagA);
    const uint32_t sbB = smem_u32(stagB);

    const int tid  = threadIdx.x;
    const int warp = tid >> 5;
    const int lane = tid & 31;
    const int gid  = lane >> 2;   // group id (row within fragment)
    const int tig  = lane & 3;    // thread in group

    const int base = blockIdx.x * E_TILE;

    // ---- preamble: indices / scalars into smem ----
    if (tid < E_TILE) {
        int e = base + tid;
        if (e >= E) e = E - 1;
        s_src[tid] = src_nodes[e];
        s_dst[tid] = dst_nodes[e];
        s_eid[tid] = event_indices[e];
        s_dt[tid]  = timestamps[e] - last_update[nidx[e]];
    }
    if (tid < 128) { s_frq[tid] = freq[tid]; s_phs[tid] = phase[tid]; }
    for (int i = tid; i < 512; i += THREADS) s_b1[i] = b1[i];
    if (tid < 256) s_b2[tid] = b2[tid];
    __syncthreads();

    // ---- async gather issue: src -> stagA (G0), dst -> stagB (G1) ----
    #pragma unroll
    for (int i = 0; i < 8; i++) {
        int lin = i * 256 + tid;
        int row = lin >> 5;
        int q   = lin & 31;
        cp16(sbA + (row * STAG_PITCH + q * 4) * 4,
             node_emb + (size_t)s_src[row] * 128 + q * 4);
    }
    CP_COMMIT();   // G0
    #pragma unroll
    for (int i = 0; i < 8; i++) {
        int lin = i * 256 + tid;
        int row = lin >> 5;
        int q   = lin & 31;
        cp16(sbB + (row * STAG_PITCH + q * 4) * 4,
             node_emb + (size_t)s_dst[row] * 128 + q * 4);
    }
    CP_COMMIT();   // G1

    // ---- chunk 2 (time encoding): compute cos directly in fragment layout ----
    #pragma unroll
    for (int i = 0; i < 8; i++) {
        int f   = i * 8 + warp;
        int mt  = f >> 4;
        int ksl = f & 15;
        int ra = mt * 16 + gid;
        int ca = ksl * 8 + tig;
        float dt0 = s_dt[ra], dt1 = s_dt[ra + 8];
        float f0 = s_frq[ca], f4 = s_frq[ca + 4];
        float p0 = s_phs[ca], p4 = s_phs[ca + 4];
        uint4 u;
        u.x = f2tf32(cosf(__fmaf_rn(dt0, f0, p0)));
        u.y = f2tf32(cosf(__fmaf_rn(dt1, f0, p0)));
        u.z = f2tf32(cosf(__fmaf_rn(dt0, f4, p4)));
        u.w = f2tf32(cosf(__fmaf_rn(dt1, f4, p4)));
        *(uint4*)(sA + ((mt * 64 + 32 + ksl) * 32 + lane) * 4) = u;
    }

    // ---- repack helper (reads staging, rounds to tf32, writes fragments) ----
    auto repack = [&](float* stag, int chunk) {
        #pragma unroll
        for (int i = 0; i < 8; i++) {
            int f   = i * 8 + warp;
            int mt  = f >> 4;
            int ksl = f & 15;
            int ra = mt * 16 + gid;
            int ca = ksl * 8 + tig;
            uint4 u;
            u.x = f2tf32(stag[ra * STAG_PITCH + ca]);
            u.y = f2tf32(stag[(ra + 8) * STAG_PITCH + ca]);
            u.z = f2tf32(stag[ra * STAG_PITCH + ca + 4]);
            u.w = f2tf32(stag[(ra + 8) * STAG_PITCH + ca + 4]);
            *(uint4*)(sA + ((mt * 64 + chunk * 16 + ksl) * 32 + lane) * 4) = u;
        }
    };

    CP_WAIT(1);          // G0 (src) landed
    __syncthreads();
    repack(stagA, 0);    // src -> chunk 0
    __syncthreads();     // stagA free

    // ---- feats -> stagA (G2) ----
    #pragma unroll
    for (int i = 0; i < 8; i++) {
        int lin = i * 256 + tid;
        int row = lin >> 5;
        int q   = lin & 31;
        cp16(sbA + (row * STAG_PITCH + q * 4) * 4,
             feats + (size_t)s_eid[row] * 128 + q * 4);
    }
    CP_COMMIT();   // G2

    CP_WAIT(1);          // G1 (dst) landed (G2 may be pending)
    __syncthreads();
    repack(stagB, 1);    // dst -> chunk 1

    CP_WAIT(0);          // G2 (feats) landed
    __syncthreads();
    repack(stagA, 3);    // feats -> chunk 3
    __syncthreads();

    // ---- GEMM1: h[64x512] = msg @ W1 ; N-slice 64 per warp ----
    float acc[4][8][4];
    #pragma unroll
    for (int mt = 0; mt < 4; mt++)
        #pragma unroll
        for (int nt = 0; nt < 8; nt++)
            #pragma unroll
            for (int r = 0; r < 4; r++) acc[mt][nt][r] = 0.0f;

    {
        const float* bbase = g_W1F + (size_t)(warp * 8) * 4096;
        float2 bbuf[2][8];
        #pragma unroll
        for (int nt = 0; nt < 8; nt++) {
            bbuf[0][nt] = *(const float2*)(bbase + (nt * 64 + 0) * 64 + lane * 2);
            bbuf[1][nt] = *(const float2*)(bbase + (nt * 64 + 1) * 64 + lane * 2);
        }
        #pragma unroll 2
        for (int ks = 0; ks < 64; ks++) {
            float2 bu[8];
            #pragma unroll
            for (int nt = 0; nt < 8; nt++) bu[nt] = bbuf[ks & 1][nt];
            if (ks < 62) {
                #pragma unroll
                for (int nt = 0; nt < 8; nt++)
                    bbuf[ks & 1][nt] =
                        *(const float2*)(bbase + (nt * 64 + ks + 2) * 64 + lane * 2);
            }
            uint4 a[4];
            #pragma unroll
            for (int mt = 0; mt < 4; mt++)
                a[mt] = *(const uint4*)(sA + ((mt * 64 + ks) * 32 + lane) * 4);
            #pragma unroll
            for (int mt = 0; mt < 4; mt++)
                #pragma unroll
                for (int nt = 0; nt < 8; nt++)
                    mma8(acc[mt][nt], a[mt], bu[nt]);
        }
    }

    // ---- relu + b1, write h back into A region (fragment-major) ----
    __syncthreads();   // everyone done reading msg A
    #pragma unroll
    for (int mt = 0; mt < 4; mt++) {
        #pragma unroll
        for (int nt = 0; nt < 8; nt++) {
            #pragma unroll
            for (int cr = 0; cr < 4; cr++) {
                int row = mt * 16 + gid + 8 * (cr >> 1);
                int n   = warp * 64 + nt * 8 + 2 * tig + (cr & 1);
                float v = fmaxf(acc[mt][nt][cr] + s_b1[n], 0.0f);
                int r15 = row & 15;
                int ks  = n >> 3;
                int c0  = n & 7;
                int l2  = (r15 & 7) * 4 + (c0 & 3);
                int rg  = (r15 >> 3) + 2 * (c0 >> 2);
                sA[((mt * 64 + ks) * 32 + l2) * 4 + rg] =
                    __uint_as_float(f2tf32(v));
            }
        }
    }
    __syncthreads();

    // ---- GEMM2: out[64x256] = h @ W2 ; N-slice 32 per warp ----
    float acc2[4][4][4];
    #pragma unroll
    for (int mt = 0; mt < 4; mt++)
        #pragma unroll
        for (int nt = 0; nt < 4; nt++)
            #pragma unroll
            for (int r = 0; r < 4; r++) acc2[mt][nt][r] = 0.0f;

    {
        const float* bbase = g_W2F + (size_t)(warp * 4) * 4096;
        float2 bbuf[2][4];
        #pragma unroll
        for (int nt = 0; nt < 4; nt++) {
            bbuf[0][nt] = *(const float2*)(bbase + (nt * 64 + 0) * 64 + lane * 2);
            bbuf[1][nt] = *(const float2*)(bbase + (nt * 64 + 1) * 64 + lane * 2);
        }
        #pragma unroll 2
        for (int ks = 0; ks < 64; ks++) {
            float2 bu[4];
            #pragma unroll
            for (int nt = 0; nt < 4; nt++) bu[nt] = bbuf[ks & 1][nt];
            if (ks < 62) {
                #pragma unroll
                for (int nt = 0; nt < 4; nt++)
                    bbuf[ks & 1][nt] =
                        *(const float2*)(bbase + (nt * 64 + ks + 2) * 64 + lane * 2);
            }
            uint4 a[4];
            #pragma unroll
            for (int mt = 0; mt < 4; mt++)
                a[mt] = *(const uint4*)(sA + ((mt * 64 + ks) * 32 + lane) * 4);
            #pragma unroll
            for (int mt = 0; mt < 4; mt++)
                #pragma unroll
                for (int nt = 0; nt < 4; nt++)
                    mma8(acc2[mt][nt], a[mt], bu[nt]);
        }
    }

    // ---- epilogue: + b2, store ----
    #pragma unroll
    for (int mt = 0; mt < 4; mt++) {
        #pragma unroll
        for (int nt = 0; nt < 4; nt++) {
            int n  = warp * 32 + nt * 8 + 2 * tig;
            float bx = s_b2[n], by = s_b2[n + 1];
            int r0 = mt * 16 + gid;
            int e0 = base + r0;
            if (e0 < E) {
                float2 o;
                o.x = acc2[mt][nt][0] + bx;
                o.y = acc2[mt][nt][1] + by;
                *(float2*)(out + (size_t)e0 * 256 + n) = o;
            }
            int e1 = base + r0 + 8;
            if (e1 < E) {
                float2 o;
                o.x = acc2[mt][nt][2] + bx;
                o.y = acc2[mt][nt][3] + by;
                *(float2*)(out + (size_t)e1 * 256 + n) = o;
            }
        }
    }
}

// ------------------------------- launch ------------------------------------

extern "C" void kernel_launch(void* const* d_in, const int* in_sizes, int n_in,
                              void* d_out, int out_size) {
    const int*   src_nodes     = (const int*)d_in[0];
    const int*   dst_nodes     = (const int*)d_in[1];
    const float* timestamps    = (const float*)d_in[2];
    const int*   event_indices = (const int*)d_in[3];
    const int*   nidx          = (const int*)d_in[4];
    const float* node_emb      = (const float*)d_in[5];
    const float* last_update   = (const float*)d_in[6];
    const float* feats         = (const float*)d_in[7];
    const float* freq          = (const float*)d_in[8];
    const float* phase         = (const float*)d_in[9];
    const float* W1            = (const float*)d_in[10];
    const float* b1v           = (const float*)d_in[11];
    const float* W2            = (const float*)d_in[12];
    const float* b2v           = (const float*)d_in[13];
    float* out = (float*)d_out;

    int E = in_sizes[0];

    cudaFuncSetAttribute(tgn_msg_kernel,
                         cudaFuncAttributeMaxDynamicSharedMemorySize, SMEM_BYTES);

    prep_weights_kernel<<<128, 256>>>(W1, W2);

    int nblk = (E + E_TILE - 1) / E_TILE;
    tgn_msg_kernel<<<nblk, THREADS, SMEM_BYTES>>>(
        src_nodes, dst_nodes, timestamps, event_indices, nidx,
        node_emb, last_update, feats, freq, phase, b1v, b2v, out, E);
}